// round 10
// baseline (speedup 1.0000x reference)
#include <cuda_runtime.h>
#include <cuda_bf16.h>
#include <cstdint>

// Problem constants
#define BATCH     4
#define SEQ       1024
#define EMB       1024
#define NHEADS    16
#define HDIM      64
#define QKV_COLS  (3 * NHEADS * HDIM)   // 3072
#define ROWS      (BATCH * SEQ)         // 4096

// Scratch (allocation-free rule: __device__ globals)
__device__ float g_qkv[ROWS * QKV_COLS];        // 4096 x 3072 (tf32-rounded)
__device__ float g_att[ROWS * EMB];             // 4096 x 1024 (tf32-rounded)
__device__ float g_xr[ROWS * EMB];              // tf32-rounded x
__device__ float g_wqkvT[QKV_COLS * EMB];       // tf32-rounded W_qkv^T [N][K]
__device__ float g_woutT[EMB * EMB];            // tf32-rounded W_out^T [N][K]

__device__ __forceinline__ uint32_t f2tf32(float x) {
    uint32_t u;
    asm("cvt.rna.tf32.f32 %0, %1;" : "=r"(u) : "f"(x));
    return u;
}
__device__ __forceinline__ float f2tf32f(float x) {
    return __uint_as_float(f2tf32(x));
}

__device__ __forceinline__ void mma_tf32(float c[4], const uint32_t a[4], const uint32_t b[2]) {
    asm volatile(
        "mma.sync.aligned.m16n8k8.row.col.f32.tf32.tf32.f32 "
        "{%0,%1,%2,%3},{%4,%5,%6,%7},{%8,%9},{%0,%1,%2,%3};"
        : "+f"(c[0]), "+f"(c[1]), "+f"(c[2]), "+f"(c[3])
        : "r"(a[0]), "r"(a[1]), "r"(a[2]), "r"(a[3]), "r"(b[0]), "r"(b[1]));
}

// ldmatrix x4: viewed as b32 8x4 matrices, lane l of matrix m gets M[l/4][l%4]
// == exact tf32 m16n8k8 fragment distribution.
__device__ __forceinline__ void ldsm_x4(uint32_t& r0, uint32_t& r1,
                                        uint32_t& r2, uint32_t& r3, uint32_t addr) {
    asm volatile("ldmatrix.sync.aligned.m8n8.x4.shared.b16 {%0,%1,%2,%3}, [%4];"
                 : "=r"(r0), "=r"(r1), "=r"(r2), "=r"(r3) : "r"(addr));
}

__device__ __forceinline__ void cp_async16(uint32_t dst, const void* src) {
    asm volatile("cp.async.cg.shared.global [%0], [%1], 16;" :: "r"(dst), "l"(src));
}
__device__ __forceinline__ void cp_commit() {
    asm volatile("cp.async.commit_group;");
}
template <int N>
__device__ __forceinline__ void cp_wait() {
    asm volatile("cp.async.wait_group %0;" :: "n"(N));
}

// ===========================================================================
// Prepass A: tf32-round x (grid-stride float4)
// ===========================================================================
__global__ void round_x(const float4* __restrict__ s, float4* __restrict__ d, int n4)
{
    for (int i = blockIdx.x * blockDim.x + threadIdx.x; i < n4;
         i += gridDim.x * blockDim.x) {
        float4 v = s[i];
        v.x = f2tf32f(v.x); v.y = f2tf32f(v.y);
        v.z = f2tf32f(v.z); v.w = f2tf32f(v.w);
        d[i] = v;
    }
}

// ===========================================================================
// Prepass B: W[K][N] fp32 -> WT[N][K] tf32-rounded fp32
// ===========================================================================
__global__ void transpose_round(const float* __restrict__ W, float* __restrict__ WT,
                                int K, int N)
{
    __shared__ float tile[32][33];
    const int tx = threadIdx.x, ty = threadIdx.y;
    const int k0 = blockIdx.y * 32, n0 = blockIdx.x * 32;
    #pragma unroll
    for (int i = 0; i < 4; i++)
        tile[ty + i * 8][tx] = W[(size_t)(k0 + ty + i * 8) * N + n0 + tx];
    __syncthreads();
    #pragma unroll
    for (int i = 0; i < 4; i++)
        WT[(size_t)(n0 + ty + i * 8) * K + k0 + tx] = f2tf32f(tile[tx][ty + i * 8]);
}

// ===========================================================================
// TF32 mma.sync GEMM with LDSM fragment loads.
//   C[M,N] = A[M,K] @ B, with B given TRANSPOSED as BT[N][K].
// Both smem tiles are [128 rows][32 cols] fp32, row stride 36 words
// (36 % 32 == 4 -> ldmatrix segments partition all banks).
// CTA 128x128x32, 8 warps (warp tile 64x32), 3-stage cp.async, 2 CTAs/SM.
// ===========================================================================
#define GBM 128
#define GBN 128
#define GBK 32
#define STG 3
#define TSTRIDE 36
#define TBUF (128 * TSTRIDE)                    // words per tile buffer
#define GEMM_SMEM (STG * 2 * TBUF * 4)          // 110592 bytes

template <bool ROUND_STORE>
__global__ __launch_bounds__(256, 2) void mma_gemm_bias(
    int M, int N, int K,
    const float* __restrict__ A,
    const float* __restrict__ BT,
    const float* __restrict__ bias,
    float* __restrict__ C)
{
    extern __shared__ float smf[];
    float* As = smf;                   // [STG][128][TSTRIDE]
    float* Bs = smf + STG * TBUF;      // [STG][128][TSTRIDE]
    const uint32_t sAs = (uint32_t)__cvta_generic_to_shared(As);
    const uint32_t sBs = (uint32_t)__cvta_generic_to_shared(Bs);

    const int t    = threadIdx.x;
    const int lane = t & 31;
    const int warp = t >> 5;
    const int wm   = warp >> 2;   // 0..1
    const int wn   = warp & 3;    // 0..3
    const int grp  = lane >> 2;
    const int qid  = lane & 3;

    const int mm = lane >> 3;     // ldmatrix matrix index 0..3
    const int rr = lane & 7;      // row within matrix
    // byte offsets of this lane's ldmatrix row address
    const uint32_t a_lane = (uint32_t)(((rr + 8 * (mm & 1)) * TSTRIDE + 4 * (mm >> 1)) * 4);
    const uint32_t b_lane = (uint32_t)(((rr + 8 * (mm >> 1)) * TSTRIDE + 4 * (mm & 1)) * 4);

    const int bm = blockIdx.y * GBM;
    const int bn = blockIdx.x * GBN;

    // staging: 2 threads per row; each stages 4 x 16B segments
    // row = t>>1, segments (t&1)*4 .. (t&1)*4+3  -> full 8 segs = 128B/row
    const int srow = t >> 1;
    const int sseg = (t & 1) * 4;

    auto issue = [&](int buf, int kt) {
        const float* Ag = A  + (size_t)(bm + srow) * K + kt * GBK;
        const float* Bg = BT + (size_t)(bn + srow) * K + kt * GBK;
        #pragma unroll
        for (int s = 0; s < 4; s++) {
            int seg = sseg + s;
            cp_async16(sAs + (uint32_t)(buf * TBUF + srow * TSTRIDE + seg * 4) * 4,
                       Ag + seg * 4);
            cp_async16(sBs + (uint32_t)(buf * TBUF + srow * TSTRIDE + seg * 4) * 4,
                       Bg + seg * 4);
        }
    };

    float c[4][4][4];
    #pragma unroll
    for (int mi = 0; mi < 4; mi++)
        #pragma unroll
        for (int ni = 0; ni < 4; ni++)
            #pragma unroll
            for (int r = 0; r < 4; r++)
                c[mi][ni][r] = 0.0f;

    issue(0, 0); cp_commit();
    issue(1, 1); cp_commit();

    const int NT = K / GBK;
    for (int kt = 0; kt < NT; kt++) {
        if (kt + STG - 1 < NT) cp_wait<STG - 2>();
        else                   cp_wait<0>();
        __syncthreads();

        if (kt + STG - 1 < NT) {
            issue((kt + STG - 1) % STG, kt + STG - 1);
            cp_commit();
        }

        const int cur = kt % STG;
        const uint32_t aw = sAs + (uint32_t)(cur * TBUF + wm * 64 * TSTRIDE) * 4 + a_lane;
        const uint32_t bw = sBs + (uint32_t)(cur * TBUF + wn * 32 * TSTRIDE) * 4 + b_lane;

        #pragma unroll
        for (int ks = 0; ks < 4; ks++) {
            const uint32_t kb4 = (uint32_t)(ks * 8 * 4);
            uint32_t af[4][4], bf[4][2];
            #pragma unroll
            for (int mi = 0; mi < 4; mi++)
                ldsm_x4(af[mi][0], af[mi][1], af[mi][2], af[mi][3],
                        aw + (uint32_t)(mi * 16 * TSTRIDE * 4) + kb4);
            #pragma unroll
            for (int p = 0; p < 2; p++)
                ldsm_x4(bf[2 * p][0], bf[2 * p][1], bf[2 * p + 1][0], bf[2 * p + 1][1],
                        bw + (uint32_t)(p * 16 * TSTRIDE * 4) + kb4);
            #pragma unroll
            for (int mi = 0; mi < 4; mi++)
                #pragma unroll
                for (int ni = 0; ni < 4; ni++)
                    mma_tf32(c[mi][ni], af[mi], bf[ni]);
        }
    }
    __syncthreads();

    #pragma unroll
    for (int mi = 0; mi < 4; mi++) {
        const int r0 = bm + wm * 64 + mi * 16 + grp;
        #pragma unroll
        for (int ni = 0; ni < 4; ni++) {
            const int col = bn + wn * 32 + ni * 8 + qid * 2;
            float2 bv = *(const float2*)&bias[col];
            float2 v0, v1;
            v0.x = c[mi][ni][0] + bv.x;  v0.y = c[mi][ni][1] + bv.y;
            v1.x = c[mi][ni][2] + bv.x;  v1.y = c[mi][ni][3] + bv.y;
            if (ROUND_STORE) {
                v0.x = f2tf32f(v0.x); v0.y = f2tf32f(v0.y);
                v1.x = f2tf32f(v1.x); v1.y = f2tf32f(v1.y);
            }
            *(float2*)&C[(size_t)r0 * N + col]       = v0;
            *(float2*)&C[(size_t)(r0 + 8) * N + col] = v1;
        }
    }
}

// ===========================================================================
// Tensor-core flash attention (tf32 mma.sync) with LDSM fragment loads.
// Ks/Vt/Ps all row stride 68 words (68 % 32 == 4 -> conflict-free LDSM).
// ===========================================================================
#define AKT 64
#define ASTR 68
#define ATT_SMEM ((2 * AKT * ASTR + 128 * ASTR) * 4)   // 69632 bytes

__global__ __launch_bounds__(256, 2) void attn_mma_kernel()
{
    extern __shared__ float smaf[];
    float* Ks = smaf;                  // [64][ASTR]   K tile: [key][d]
    float* Vt = smaf + AKT * ASTR;     // [64][ASTR]   V^T:   [d][key]
    float* Ps = smaf + 2 * AKT * ASTR; // [128][ASTR]  P / Q staging
    const uint32_t sKs = (uint32_t)__cvta_generic_to_shared(Ks);
    const uint32_t sVt = (uint32_t)__cvta_generic_to_shared(Vt);
    const uint32_t sPs = (uint32_t)__cvta_generic_to_shared(Ps);

    const int t    = threadIdx.x;
    const int lane = t & 31;
    const int warp = t >> 5;
    const int g8   = lane >> 2;
    const int qid  = lane & 3;

    const int mm = lane >> 3;
    const int rr = lane & 7;
    const uint32_t aL = (uint32_t)((((mm & 1) * 8 + rr) * ASTR + 4 * (mm >> 1)) * 4);
    const uint32_t bL = (uint32_t)((((mm >> 1) * 8 + rr) * ASTR + 4 * (mm & 1)) * 4);

    const int bh = blockIdx.y;
    const int b  = bh >> 4;
    const int h  = bh & 15;
    const int hoff  = h * HDIM;
    const int qrow0 = blockIdx.x * 128;

    const size_t rowStride = QKV_COLS;
    const float* Kg = g_qkv + (size_t)b * SEQ * rowStride + hoff;              // K third
    const float* Vg = Kg + 2 * EMB;                                            // V third
    const float* Qg = g_qkv + ((size_t)b * SEQ + qrow0) * rowStride + EMB + hoff;

    // ---- stage Q (x0.125 exact exponent shift) ----
    {
        const int j     = t >> 1;
        const int cbase = (t & 1) * 32;
        #pragma unroll
        for (int p = 0; p < 8; p++) {
            float4 v = *(const float4*)&Qg[(size_t)j * rowStride + cbase + p * 4];
            v.x *= 0.125f; v.y *= 0.125f; v.z *= 0.125f; v.w *= 0.125f;
            *(float4*)&Ps[j * ASTR + cbase + p * 4] = v;
        }
    }
    __syncthreads();

    // ---- load Q fragments (held in regs; one-time, ldmatrix) ----
    uint32_t qa[8][4];
    {
        const uint32_t qw = sPs + (uint32_t)(warp * 16 * ASTR * 4) + aL;
        #pragma unroll
        for (int ks = 0; ks < 8; ks++)
            ldsm_x4(qa[ks][0], qa[ks][1], qa[ks][2], qa[ks][3],
                    qw + (uint32_t)(ks * 8 * 4));
    }
    __syncthreads();

    float oc[8][4];
    #pragma unroll
    for (int ni = 0; ni < 8; ni++)
        #pragma unroll
        for (int r = 0; r < 4; r++) oc[ni][r] = 0.0f;
    float lsum0 = 0.0f, lsum1 = 0.0f;

    const int vj = t & 63;
    const int vc = (t >> 6) * 4;

    for (int kt = 0; kt < SEQ / AKT; kt++) {
        const float* Kn = Kg + (size_t)kt * AKT * rowStride;
        const float* Vn = Vg + (size_t)kt * AKT * rowStride;
        #pragma unroll
        for (int p = 0; p < 4; p++) {
            int e = t + p * 256;
            int j = e >> 4, c4 = (e & 15) * 4;
            *(float4*)&Ks[j * ASTR + c4] =
                *(const float4*)&Kn[(size_t)j * rowStride + c4];
        }
        #pragma unroll
        for (int p = 0; p < 4; p++) {
            int d = vc + p * 16;
            float4 v = *(const float4*)&Vn[(size_t)vj * rowStride + d];
            Vt[(d + 0) * ASTR + vj] = v.x;
            Vt[(d + 1) * ASTR + vj] = v.y;
            Vt[(d + 2) * ASTR + vj] = v.z;
            Vt[(d + 3) * ASTR + vj] = v.w;
        }
        __syncthreads();

        // ---- S = Q K^T ----
        float sc[8][4];
        #pragma unroll
        for (int ni = 0; ni < 8; ni++)
            #pragma unroll
            for (int r = 0; r < 4; r++) sc[ni][r] = 0.0f;

        #pragma unroll
        for (int ks = 0; ks < 8; ks++) {
            const uint32_t kb4 = (uint32_t)(ks * 8 * 4);
            uint32_t bf[8][2];
            #pragma unroll
            for (int p = 0; p < 4; p++)
                ldsm_x4(bf[2 * p][0], bf[2 * p][1], bf[2 * p + 1][0], bf[2 * p + 1][1],
                        sKs + (uint32_t)(p * 16 * ASTR * 4) + kb4 + bL);
            #pragma unroll
            for (int ni = 0; ni < 8; ni++)
                mma_tf32(sc[ni], qa[ks], bf[ni]);
        }

        // ---- P = exp(S); row-sum; store P (tf32-rounded) ----
        float* Pw = Ps + (warp * 16 + g8) * ASTR;
        #pragma unroll
        for (int ni = 0; ni < 8; ni++) {
            float p0 = __expf(sc[ni][0]);
            float p1 = __expf(sc[ni][1]);
            float p2 = __expf(sc[ni][2]);
            float p3 = __expf(sc[ni][3]);
            lsum0 += p0 + p1;
            lsum1 += p2 + p3;
            float2 u0, u1;
            u0.x = f2tf32f(p0); u0.y = f2tf32f(p1);
            u1.x = f2tf32f(p2); u1.y = f2tf32f(p3);
            *(float2*)&Pw[ni * 8 + qid * 2]            = u0;
            *(float2*)&Pw[8 * ASTR + ni * 8 + qid * 2] = u1;
        }
        __syncwarp();

        // ---- O += P V ----
        const uint32_t pw = sPs + (uint32_t)(warp * 16 * ASTR * 4) + aL;
        #pragma unroll
        for (int ks = 0; ks < 8; ks++) {
            const uint32_t kb4 = (uint32_t)(ks * 8 * 4);
            uint32_t af[4];
            ldsm_x4(af[0], af[1], af[2], af[3], pw + kb4);
            uint32_t bf[8][2];
            #pragma unroll
            for (int p = 0; p < 4; p++)
                ldsm_x4(bf[2 * p][0], bf[2 * p][1], bf[2 * p + 1][0], bf[2 * p + 1][1],
                        sVt + (uint32_t)(p * 16 * ASTR * 4) + kb4 + bL);
            #pragma unroll
            for (int ni = 0; ni < 8; ni++)
                mma_tf32(oc[ni], af, bf[ni]);
        }
        __syncthreads();
    }

    // ---- normalize, round to tf32, write ----
    float l0 = lsum0, l1 = lsum1;
    #pragma unroll
    for (int m = 1; m < 4; m <<= 1) {
        l0 += __shfl_xor_sync(0xffffffffu, l0, m);
        l1 += __shfl_xor_sync(0xffffffffu, l1, m);
    }
    const float inv0 = 1.0f / l0;
    const float inv1 = 1.0f / l1;

    const int r0 = qrow0 + warp * 16 + g8;
    float* O0 = g_att + ((size_t)b * SEQ + r0) * EMB + hoff;
    float* O1 = O0 + 8 * EMB;
    #pragma unroll
    for (int ni = 0; ni < 8; ni++) {
        const int col = ni * 8 + qid * 2;
        float2 v0, v1;
        v0.x = f2tf32f(oc[ni][0] * inv0);  v0.y = f2tf32f(oc[ni][1] * inv0);
        v1.x = f2tf32f(oc[ni][2] * inv1);  v1.y = f2tf32f(oc[ni][3] * inv1);
        *(float2*)&O0[col] = v0;
        *(float2*)&O1[col] = v1;
    }
}

// ---------------------------------------------------------------------------
// Launch: inputs in order x, W_qkv, b_qkv, W_out, b_out
// ---------------------------------------------------------------------------
extern "C" void kernel_launch(void* const* d_in, const int* in_sizes, int n_in,
                              void* d_out, int out_size)
{
    const float* x     = (const float*)d_in[0];
    const float* W_qkv = (const float*)d_in[1];
    const float* b_qkv = (const float*)d_in[2];
    const float* W_out = (const float*)d_in[3];
    const float* b_out = (const float*)d_in[4];
    float*       out   = (float*)d_out;

    float *qkv_ptr, *att_ptr, *xr_ptr, *wqkvT_ptr, *woutT_ptr;
    cudaGetSymbolAddress((void**)&qkv_ptr,   g_qkv);
    cudaGetSymbolAddress((void**)&att_ptr,   g_att);
    cudaGetSymbolAddress((void**)&xr_ptr,    g_xr);
    cudaGetSymbolAddress((void**)&wqkvT_ptr, g_wqkvT);
    cudaGetSymbolAddress((void**)&woutT_ptr, g_woutT);

    static bool attr_set = false;
    if (!attr_set) {
        cudaFuncSetAttribute(mma_gemm_bias<true>,
                             cudaFuncAttributeMaxDynamicSharedMemorySize, GEMM_SMEM);
        cudaFuncSetAttribute(mma_gemm_bias<false>,
                             cudaFuncAttributeMaxDynamicSharedMemorySize, GEMM_SMEM);
        cudaFuncSetAttribute(attn_mma_kernel,
                             cudaFuncAttributeMaxDynamicSharedMemorySize, ATT_SMEM);
        attr_set = true;
    }

    // 0) Prepasses: round x; transpose+round weights to [N][K]
    round_x<<<512, 256>>>((const float4*)x, (float4*)xr_ptr, ROWS * EMB / 4);
    {
        dim3 blk(32, 8);
        transpose_round<<<dim3(QKV_COLS / 32, EMB / 32), blk>>>(W_qkv, wqkvT_ptr, EMB, QKV_COLS);
        transpose_round<<<dim3(EMB / 32, EMB / 32), blk>>>(W_out, woutT_ptr, EMB, EMB);
    }

    // 1) QKV projection (output tf32-rounded for attention)
    {
        dim3 grid(QKV_COLS / GBN, ROWS / GBM);   // (24, 32)
        mma_gemm_bias<true><<<grid, 256, GEMM_SMEM>>>(
            ROWS, QKV_COLS, EMB, xr_ptr, wqkvT_ptr, b_qkv, qkv_ptr);
    }

    // 2) Attention (tensor-core; output tf32-rounded for out-proj)
    {
        dim3 grid(SEQ / 128, BATCH * NHEADS);    // (8, 64)
        attn_mma_kernel<<<grid, 256, ATT_SMEM>>>();
    }

    // 3) Output projection (full fp32 output)
    {
        dim3 grid(EMB / GBN, ROWS / GBM);        // (8, 32)
        mma_gemm_bias<false><<<grid, 256, GEMM_SMEM>>>(
            ROWS, EMB, EMB, att_ptr, woutT_ptr, b_out, out);
    }
}

// round 11
// speedup vs baseline: 2.1742x; 2.1742x over previous
#include <cuda_runtime.h>
#include <cuda_fp16.h>
#include <cstdint>

// Problem constants
#define BATCH     4
#define SEQ       1024
#define EMB       1024
#define NHEADS    16
#define HDIM      64
#define QKV_COLS  (3 * NHEADS * HDIM)   // 3072
#define ROWS      (BATCH * SEQ)         // 4096

// Scratch (allocation-free rule: __device__ globals)
__device__ __half g_qkv[ROWS * QKV_COLS];   // fp16 QKV (GEMM1 out)
__device__ __half g_att[ROWS * EMB];        // fp16 attention out
__device__ __half g_xh[ROWS * EMB];         // fp16 x
__device__ __half g_wqkvh[EMB * QKV_COLS];  // fp16 W_qkv [K][N]
__device__ __half g_wouth[EMB * EMB];       // fp16 W_out [K][N]

// ---------------------------------------------------------------------------
// Helpers
// ---------------------------------------------------------------------------
__device__ __forceinline__ void mma_f16(float c[4], const uint32_t a[4], const uint32_t b[2]) {
    asm volatile(
        "mma.sync.aligned.m16n8k16.row.col.f32.f16.f16.f32 "
        "{%0,%1,%2,%3},{%4,%5,%6,%7},{%8,%9},{%0,%1,%2,%3};"
        : "+f"(c[0]), "+f"(c[1]), "+f"(c[2]), "+f"(c[3])
        : "r"(a[0]), "r"(a[1]), "r"(a[2]), "r"(a[3]), "r"(b[0]), "r"(b[1]));
}
__device__ __forceinline__ void ldsm_x4(uint32_t& r0, uint32_t& r1,
                                        uint32_t& r2, uint32_t& r3, uint32_t addr) {
    asm volatile("ldmatrix.sync.aligned.m8n8.x4.shared.b16 {%0,%1,%2,%3}, [%4];"
                 : "=r"(r0), "=r"(r1), "=r"(r2), "=r"(r3) : "r"(addr));
}
__device__ __forceinline__ void ldsm_x4t(uint32_t& r0, uint32_t& r1,
                                         uint32_t& r2, uint32_t& r3, uint32_t addr) {
    asm volatile("ldmatrix.sync.aligned.m8n8.x4.trans.shared.b16 {%0,%1,%2,%3}, [%4];"
                 : "=r"(r0), "=r"(r1), "=r"(r2), "=r"(r3) : "r"(addr));
}
// pack two fp32 -> fp16x2 (lo = first arg)
__device__ __forceinline__ uint32_t pack_h2(float lo, float hi) {
    uint32_t r;
    asm("cvt.rn.f16x2.f32 %0, %1, %2;" : "=r"(r) : "f"(hi), "f"(lo));
    return r;
}
__device__ __forceinline__ void cp_async16(uint32_t dst, const void* src) {
    asm volatile("cp.async.cg.shared.global [%0], [%1], 16;" :: "r"(dst), "l"(src));
}
__device__ __forceinline__ void cp_commit() {
    asm volatile("cp.async.commit_group;");
}
template <int N>
__device__ __forceinline__ void cp_wait() {
    asm volatile("cp.async.wait_group %0;" :: "n"(N));
}

// ---------------------------------------------------------------------------
// Prepass: fp32 -> fp16 convert (float2 -> half2 grid-stride)
// ---------------------------------------------------------------------------
__global__ void f2h(const float2* __restrict__ s, __half2* __restrict__ d, int n2)
{
    for (int i = blockIdx.x * blockDim.x + threadIdx.x; i < n2;
         i += gridDim.x * blockDim.x) {
        float2 v = s[i];
        d[i] = __floats2half2_rn(v.x, v.y);
    }
}

// ===========================================================================
// fp16 m16n8k16 GEMM, fused bias: C[M,N] = A[M,K] @ B[K,N] + bias
// A [M][K] fp16, B [K][N] fp16 (natural layout; B staging fully coalesced).
// A frags: ldmatrix.x4; B frags: ldmatrix.x4.trans.
// Smem strides: A 56 halves (112B: 16B-aligned rows; 28-word stride -> bank
// partition), B 136 halves (272B; 68 words -> partition).
// CTA 128x128x32, 8 warps (warp 64x32), 3-stage cp.async, 2 CTAs/SM.
// ===========================================================================
#define GBM 128
#define GBN 128
#define GBK 32
#define STG 3
#define SA  56
#define SB  136
#define ABUFH (128 * SA)                  // 7168 halves
#define BBUFH (32 * SB)                   // 4352 halves
#define GEMM_SMEM (STG * (ABUFH + BBUFH) * 2)   // 69120 bytes

template <bool OUT32>
__global__ __launch_bounds__(256, 2) void hgemm_bias(
    int M, int N, int K,
    const __half* __restrict__ A,
    const __half* __restrict__ B,
    const float* __restrict__ bias,
    void* __restrict__ Cout)
{
    extern __shared__ __half smh[];
    __half* As = smh;
    __half* Bs = smh + STG * ABUFH;
    const uint32_t sA = (uint32_t)__cvta_generic_to_shared(As);
    const uint32_t sB = (uint32_t)__cvta_generic_to_shared(Bs);

    const int t    = threadIdx.x;
    const int lane = t & 31;
    const int warp = t >> 5;
    const int wm   = warp >> 2;   // 0..1
    const int wn   = warp & 3;    // 0..3
    const int grp  = lane >> 2;
    const int qid  = lane & 3;
    const int mm   = lane >> 3;   // ldmatrix matrix id 0..3
    const int rr   = lane & 7;

    // lane base offsets (halves) for ldmatrix row addresses
    const uint32_t aL = (uint32_t)((rr + 8 * (mm & 1)) * SA + 8 * (mm >> 1));
    const uint32_t bL = (uint32_t)((rr + 8 * (mm & 1)) * SB + 8 * (mm >> 1));

    const int bm = blockIdx.y * GBM;
    const int bn = blockIdx.x * GBN;

    // staging maps (coverage verified):
    // A: 128 rows x 64B; 2 thr/row, 2x16B each -> srowA=t>>1, segs (t&1)*2+{0,1}
    // B: 32 rows x 256B; 8 thr/row, 2x16B each -> srowB=t>>3, segs (t&7)*2+{0,1}
    const int srowA = t >> 1, ssegA = (t & 1) * 2;
    const int srowB = t >> 3, ssegB = (t & 7) * 2;

    auto issue = [&](int buf, int kt) {
        const __half* Ag = A + (size_t)(bm + srowA) * K + kt * GBK;
        const __half* Bg = B + (size_t)(kt * GBK + srowB) * N + bn;
        #pragma unroll
        for (int s = 0; s < 2; s++) {
            int seg = ssegA + s;
            cp_async16(sA + (uint32_t)(buf * ABUFH + srowA * SA + seg * 8) * 2,
                       Ag + seg * 8);
        }
        #pragma unroll
        for (int s = 0; s < 2; s++) {
            int seg = ssegB + s;
            cp_async16(sB + (uint32_t)(buf * BBUFH + srowB * SB + seg * 8) * 2,
                       Bg + seg * 8);
        }
    };

    float c[4][4][4];
    #pragma unroll
    for (int mi = 0; mi < 4; mi++)
        #pragma unroll
        for (int ni = 0; ni < 4; ni++)
            #pragma unroll
            for (int r = 0; r < 4; r++)
                c[mi][ni][r] = 0.0f;

    issue(0, 0); cp_commit();
    issue(1, 1); cp_commit();

    const int NT = K / GBK;
    for (int kt = 0; kt < NT; kt++) {
        if (kt + STG - 1 < NT) cp_wait<STG - 2>();
        else                   cp_wait<0>();
        __syncthreads();

        if (kt + STG - 1 < NT) {
            issue((kt + STG - 1) % STG, kt + STG - 1);
            cp_commit();
        }

        const int cur = kt % STG;
        const uint32_t aw = sA + (uint32_t)(cur * ABUFH + wm * 64 * SA + aL) * 2;
        const uint32_t bw = sB + (uint32_t)(cur * BBUFH + wn * 32 + bL) * 2;

        #pragma unroll
        for (int ks = 0; ks < 2; ks++) {
            uint32_t af[4][4], bf[4][2];
            #pragma unroll
            for (int mi = 0; mi < 4; mi++)
                ldsm_x4(af[mi][0], af[mi][1], af[mi][2], af[mi][3],
                        aw + (uint32_t)(mi * 16 * SA + ks * 16) * 2);
            #pragma unroll
            for (int ni2 = 0; ni2 < 2; ni2++)
                ldsm_x4t(bf[2 * ni2][0], bf[2 * ni2][1],
                         bf[2 * ni2 + 1][0], bf[2 * ni2 + 1][1],
                         bw + (uint32_t)(ks * 16 * SB + ni2 * 16) * 2);
            #pragma unroll
            for (int mi = 0; mi < 4; mi++)
                #pragma unroll
                for (int ni = 0; ni < 4; ni++)
                    mma_f16(c[mi][ni], af[mi], bf[ni]);
        }
    }
    __syncthreads();

    // epilogue
    #pragma unroll
    for (int mi = 0; mi < 4; mi++) {
        const int r0 = bm + wm * 64 + mi * 16 + grp;
        #pragma unroll
        for (int ni = 0; ni < 4; ni++) {
            const int col = bn + wn * 32 + ni * 8 + qid * 2;
            float2 bv = *(const float2*)&bias[col];
            float x0 = c[mi][ni][0] + bv.x, x1 = c[mi][ni][1] + bv.y;
            float x2 = c[mi][ni][2] + bv.x, x3 = c[mi][ni][3] + bv.y;
            if (OUT32) {
                float* C = (float*)Cout;
                *(float2*)&C[(size_t)r0 * N + col]       = make_float2(x0, x1);
                *(float2*)&C[(size_t)(r0 + 8) * N + col] = make_float2(x2, x3);
            } else {
                __half* C = (__half*)Cout;
                *(uint32_t*)&C[(size_t)r0 * N + col]       = pack_h2(x0, x1);
                *(uint32_t*)&C[(size_t)(r0 + 8) * N + col] = pack_h2(x2, x3);
            }
        }
    }
}

// ===========================================================================
// fp16 flash attention: O = softmax(QK^T/8)V per (b,h).
// CTA: 128 q rows, 8 warps (16 q each). 64-key tiles, single-buffered.
// K,V staged [row][72h] (16B-aligned rows, 36-word stride -> bank partition).
// QK: B frags via ldmatrix non-trans on K[key][d].
// PV: P stays IN REGISTERS (C-frag pairs == A-frag pairs); V frags via
//     ldmatrix.trans on V[key][d]. Scale 1/8 folded into exp argument.
// ===========================================================================
#define KSTR 72
#define ATT_SMEM ((64 * KSTR + 64 * KSTR + 128 * KSTR) * 2)   // 36864 bytes

__global__ __launch_bounds__(256, 2) void attn_f16_kernel()
{
    extern __shared__ __half sma[];
    __half* Ksm = sma;                    // [64][KSTR]
    __half* Vsm = sma + 64 * KSTR;        // [64][KSTR]
    __half* Qsm = sma + 128 * KSTR;       // [128][KSTR]
    const uint32_t sK = (uint32_t)__cvta_generic_to_shared(Ksm);
    const uint32_t sV = (uint32_t)__cvta_generic_to_shared(Vsm);
    const uint32_t sQ = (uint32_t)__cvta_generic_to_shared(Qsm);

    const int t    = threadIdx.x;
    const int lane = t & 31;
    const int warp = t >> 5;
    const int grp  = lane >> 2;
    const int qid  = lane & 3;
    const int mm   = lane >> 3;
    const int rr   = lane & 7;

    const int bh = blockIdx.y;
    const int b  = bh >> 4;
    const int h  = bh & 15;
    const int hoff  = h * HDIM;
    const int qrow0 = blockIdx.x * 128;

    const int rowStride = QKV_COLS;
    const __half* Kg = g_qkv + (size_t)b * SEQ * rowStride + hoff;           // K third
    const __half* Vg = Kg + 2 * EMB;                                         // V third
    const __half* Qg = g_qkv + ((size_t)b * SEQ + qrow0) * rowStride + EMB + hoff;

    // ---- stage Q: 128 rows x 128B; 2 thr/row, 4x16B each ----
    {
        const int j  = t >> 1;
        const int s0 = (t & 1) * 4;
        #pragma unroll
        for (int p = 0; p < 4; p++) {
            int seg = s0 + p;
            *(uint4*)&Qsm[j * KSTR + seg * 8] =
                *(const uint4*)&Qg[(size_t)j * rowStride + seg * 8];
        }
    }
    __syncthreads();

    // ---- Q fragments (held in registers) ----
    uint32_t qa[4][4];
    {
        const uint32_t qw = sQ +
            (uint32_t)((warp * 16 + rr + 8 * (mm & 1)) * KSTR + 8 * (mm >> 1)) * 2;
        #pragma unroll
        for (int ks = 0; ks < 4; ks++)
            ldsm_x4(qa[ks][0], qa[ks][1], qa[ks][2], qa[ks][3],
                    qw + (uint32_t)(ks * 16) * 2);
    }

    float oc[8][4];
    #pragma unroll
    for (int ni = 0; ni < 8; ni++)
        #pragma unroll
        for (int r = 0; r < 4; r++) oc[ni][r] = 0.0f;
    float lsum0 = 0.0f, lsum1 = 0.0f;

    // K/V staging: 64 rows x 128B; 4 thr/row, 2x16B each
    const int kvrow = t >> 2;
    const int kvs0  = t & 3;

    // fragment lane offsets
    // QK B (non-trans on K[key][d]): key off 8*(mm>>1), d off 8*(mm&1)
    const uint32_t kL = (uint32_t)((rr + 8 * (mm >> 1)) * KSTR + 8 * (mm & 1));
    // PV B (trans on V[key][d]): key off 8*(mm&1), d off 8*(mm>>1)
    const uint32_t vL = (uint32_t)((rr + 8 * (mm & 1)) * KSTR + 8 * (mm >> 1));

    for (int kt = 0; kt < SEQ / 64; kt++) {
        const __half* Kn = Kg + (size_t)kt * 64 * rowStride;
        const __half* Vn = Vg + (size_t)kt * 64 * rowStride;
        #pragma unroll
        for (int p = 0; p < 2; p++) {
            int seg = kvs0 + p * 4;
            *(uint4*)&Ksm[kvrow * KSTR + seg * 8] =
                *(const uint4*)&Kn[(size_t)kvrow * rowStride + seg * 8];
            *(uint4*)&Vsm[kvrow * KSTR + seg * 8] =
                *(const uint4*)&Vn[(size_t)kvrow * rowStride + seg * 8];
        }
        __syncthreads();

        // ---- S = Q K^T (fp32 accum) ----
        float sc[8][4];
        #pragma unroll
        for (int ni = 0; ni < 8; ni++)
            #pragma unroll
            for (int r = 0; r < 4; r++) sc[ni][r] = 0.0f;

        #pragma unroll
        for (int ks = 0; ks < 4; ks++) {          // d blocks of 16
            uint32_t bf[8][2];
            #pragma unroll
            for (int ni2 = 0; ni2 < 4; ni2++)     // key blocks of 16
                ldsm_x4(bf[2 * ni2][0], bf[2 * ni2][1],
                        bf[2 * ni2 + 1][0], bf[2 * ni2 + 1][1],
                        sK + (uint32_t)(ni2 * 16 * KSTR + ks * 16 + kL) * 2);
            #pragma unroll
            for (int ni = 0; ni < 8; ni++)
                mma_f16(sc[ni], qa[ks], bf[ni]);
        }

        // ---- P = exp(S/8) in place; accumulate row sums ----
        #pragma unroll
        for (int ni = 0; ni < 8; ni++) {
            sc[ni][0] = __expf(sc[ni][0] * 0.125f);
            sc[ni][1] = __expf(sc[ni][1] * 0.125f);
            sc[ni][2] = __expf(sc[ni][2] * 0.125f);
            sc[ni][3] = __expf(sc[ni][3] * 0.125f);
            lsum0 += sc[ni][0] + sc[ni][1];
            lsum1 += sc[ni][2] + sc[ni][3];
        }

        // ---- O += P V  (P packed from registers; V via trans-ldmatrix) ----
        #pragma unroll
        for (int ks = 0; ks < 4; ks++) {          // key blocks of 16
            uint32_t af[4];
            af[0] = pack_h2(sc[2 * ks][0],     sc[2 * ks][1]);
            af[1] = pack_h2(sc[2 * ks][2],     sc[2 * ks][3]);
            af[2] = pack_h2(sc[2 * ks + 1][0], sc[2 * ks + 1][1]);
            af[3] = pack_h2(sc[2 * ks + 1][2], sc[2 * ks + 1][3]);
            uint32_t bf[8][2];
            #pragma unroll
            for (int ni2 = 0; ni2 < 4; ni2++)     // d blocks of 16
                ldsm_x4t(bf[2 * ni2][0], bf[2 * ni2][1],
                         bf[2 * ni2 + 1][0], bf[2 * ni2 + 1][1],
                         sV + (uint32_t)(ks * 16 * KSTR + ni2 * 16 + vL) * 2);
            #pragma unroll
            for (int ni = 0; ni < 8; ni++)
                mma_f16(oc[ni], af, bf[ni]);
        }
        __syncthreads();
    }

    // ---- normalize, write fp16 ----
    float l0 = lsum0, l1 = lsum1;
    #pragma unroll
    for (int m = 1; m < 4; m <<= 1) {
        l0 += __shfl_xor_sync(0xffffffffu, l0, m);
        l1 += __shfl_xor_sync(0xffffffffu, l1, m);
    }
    const float inv0 = 1.0f / l0;
    const float inv1 = 1.0f / l1;

    const int r0 = qrow0 + warp * 16 + grp;
    __half* O0 = g_att + ((size_t)b * SEQ + r0) * EMB + hoff;
    __half* O1 = O0 + 8 * EMB;
    #pragma unroll
    for (int ni = 0; ni < 8; ni++) {
        const int col = ni * 8 + qid * 2;
        *(uint32_t*)&O0[col] = pack_h2(oc[ni][0] * inv0, oc[ni][1] * inv0);
        *(uint32_t*)&O1[col] = pack_h2(oc[ni][2] * inv1, oc[ni][3] * inv1);
    }
}

// ---------------------------------------------------------------------------
// Launch: inputs in order x, W_qkv, b_qkv, W_out, b_out
// ---------------------------------------------------------------------------
extern "C" void kernel_launch(void* const* d_in, const int* in_sizes, int n_in,
                              void* d_out, int out_size)
{
    const float* x     = (const float*)d_in[0];
    const float* W_qkv = (const float*)d_in[1];
    const float* b_qkv = (const float*)d_in[2];
    const float* W_out = (const float*)d_in[3];
    const float* b_out = (const float*)d_in[4];
    float*       out   = (float*)d_out;

    __half *qkv_p, *att_p, *xh_p, *wq_p, *wo_p;
    cudaGetSymbolAddress((void**)&qkv_p, g_qkv);
    cudaGetSymbolAddress((void**)&att_p, g_att);
    cudaGetSymbolAddress((void**)&xh_p,  g_xh);
    cudaGetSymbolAddress((void**)&wq_p,  g_wqkvh);
    cudaGetSymbolAddress((void**)&wo_p,  g_wouth);

    static bool attr_set = false;
    if (!attr_set) {
        cudaFuncSetAttribute(hgemm_bias<false>,
                             cudaFuncAttributeMaxDynamicSharedMemorySize, GEMM_SMEM);
        cudaFuncSetAttribute(hgemm_bias<true>,
                             cudaFuncAttributeMaxDynamicSharedMemorySize, GEMM_SMEM);
        cudaFuncSetAttribute(attn_f16_kernel,
                             cudaFuncAttributeMaxDynamicSharedMemorySize, ATT_SMEM);
        attr_set = true;
    }

    // 0) fp32 -> fp16 prepasses
    f2h<<<512, 256>>>((const float2*)x,     (__half2*)xh_p, ROWS * EMB / 2);
    f2h<<<512, 256>>>((const float2*)W_qkv, (__half2*)wq_p, EMB * QKV_COLS / 2);
    f2h<<<256, 256>>>((const float2*)W_out, (__half2*)wo_p, EMB * EMB / 2);

    // 1) QKV projection -> fp16
    {
        dim3 grid(QKV_COLS / GBN, ROWS / GBM);   // (24, 32)
        hgemm_bias<false><<<grid, 256, GEMM_SMEM>>>(
            ROWS, QKV_COLS, EMB, xh_p, wq_p, b_qkv, qkv_p);
    }

    // 2) Attention -> fp16
    {
        dim3 grid(SEQ / 128, BATCH * NHEADS);    // (8, 64)
        attn_f16_kernel<<<grid, 256, ATT_SMEM>>>();
    }

    // 3) Output projection -> fp32
    {
        dim3 grid(EMB / GBN, ROWS / GBM);        // (8, 32)
        hgemm_bias<true><<<grid, 256, GEMM_SMEM>>>(
            ROWS, EMB, EMB, att_p, wo_p, b_out, out);
    }
}